// round 9
// baseline (speedup 1.0000x reference)
#include <cuda_runtime.h>

// out[b, idx] = prod_w ( bit_{19-w}(idx) ? sin(h[b,w]) : cos(h[b,w]) ),
// h = (x + params) * 0.5. Wire w maps to idx bit (19-w).
//
// 32768 CTAs (512 x 64 batches). CTA = (batch b, 2 contiguous hi values),
// stores one contiguous 8 KB region. Register-factored products, all stores
// __stcs (evict-first) — R8's mixed-policy experiment regressed and is reverted.

#define N_WIRES 20
#define BATCH 64
#define HI_PER_BLOCK 2
#define THREADS 256

__global__ __launch_bounds__(THREADS, 8)
void qansatz_kernel(const float* __restrict__ x,
                    const float* __restrict__ params,
                    float* __restrict__ out)
{
    __shared__ float sc[N_WIRES];
    __shared__ float ss[N_WIRES];

    const int b   = blockIdx.y;          // batch
    const int bx  = blockIdx.x;          // hi_base = 2*bx, bx in [0,512)
    const int tid = threadIdx.x;

    // 1) cos/sin for this batch's 20 wires (one barrier)
    if (tid < N_WIRES) {
        float h = (x[b * N_WIRES + tid] + params[tid]) * 0.5f;
        float c, s;
        sincosf(h, &s, &c);
        sc[tid] = c;
        ss[tid] = s;
    }
    __syncthreads();

    // 2) lo part: this thread covers lo = 4*tid + j, j=0..3.
    //    lo bit q (q=2..9) = tid bit (q-2); factor = ss[19-q] : sc[19-q].
    float lo_common = 1.0f;
    #pragma unroll
    for (int q = 2; q < 10; q++)
        lo_common *= ((tid >> (q - 2)) & 1) ? ss[19 - q] : sc[19 - q];

    float lv0 = sc[19] * sc[18];   // j=0
    float lv1 = ss[19] * sc[18];   // j=1
    float lv2 = sc[19] * ss[18];   // j=2
    float lv3 = ss[19] * ss[18];   // j=3

    // 3) hi part: hi = 2*bx + i, i=0..1.
    //    hi bit q (q=1..9) = bx bit (q-1); factor = ss[9-q] : sc[9-q].
    float hi_common = 1.0f;
    #pragma unroll
    for (int q = 1; q < 10; q++)
        hi_common *= ((bx >> (q - 1)) & 1) ? ss[9 - q] : sc[9 - q];

    // i bit0 -> wire 9
    float hv0 = sc[9];
    float hv1 = ss[9];

    float base = lo_common * hi_common;
    float c0 = base * lv0, c1 = base * lv1, c2 = base * lv2, c3 = base * lv3;

    // 4) stream out: 2 hi-values x one float4/thread (independent stores)
    size_t off = ((size_t)b << 20) + ((size_t)bx << 11);
    float4* dst = reinterpret_cast<float4*>(out + off) + tid;

    {
        float4 v;
        v.x = hv0 * c0; v.y = hv0 * c1; v.z = hv0 * c2; v.w = hv0 * c3;
        __stcs(dst, v);
    }
    {
        float4 v;
        v.x = hv1 * c0; v.y = hv1 * c1; v.z = hv1 * c2; v.w = hv1 * c3;
        __stcs(dst + 256, v);
    }
}

extern "C" void kernel_launch(void* const* d_in, const int* in_sizes, int n_in,
                              void* d_out, int out_size)
{
    const float* x      = (const float*)d_in[0];   // (64, 20)
    const float* params = (const float*)d_in[1];   // (20,)
    float* out          = (float*)d_out;           // (64, 2^20)

    dim3 grid(1024 / HI_PER_BLOCK, BATCH);         // (512, 64) = 32768 CTAs
    qansatz_kernel<<<grid, THREADS>>>(x, params, out);
}

// round 11
// speedup vs baseline: 1.0500x; 1.0500x over previous
#include <cuda_runtime.h>

// out[b, idx] = prod_w ( bit_{19-w}(idx) ? sin(h[b,w]) : cos(h[b,w]) ),
// h = (x + params) * 0.5. Wire w maps to idx bit (19-w).
//
// FINAL CANDIDATE (R7 winner, re-bench for reproducibility):
// 16384 CTAs (256 x 64 batches). CTA = (batch b, 4 contiguous hi values),
// stores one contiguous 16 KB region. All products computed in registers via
// shared-prefix factoring (lo = 4*tid+j and hi = 4*bx+i each share bits 2..9),
// so setup is ~35 muls/thread, one barrier, no smem tables. All stores are
// __stcs streaming (write-once output). Measured 40.9 us = 6.56 TB/s
// sustained write = 82% of HBM spec; granularity curve bracketed
// (8192: 41.5, 16384: 40.9, 32768: 43.0).

#define N_WIRES 20
#define BATCH 64
#define HI_PER_BLOCK 4
#define THREADS 256

__global__ __launch_bounds__(THREADS, 8)
void qansatz_kernel(const float* __restrict__ x,
                    const float* __restrict__ params,
                    float* __restrict__ out)
{
    __shared__ float sc[N_WIRES];
    __shared__ float ss[N_WIRES];

    const int b   = blockIdx.y;          // batch
    const int bx  = blockIdx.x;          // hi_base = 4*bx
    const int tid = threadIdx.x;

    // 1) cos/sin for this batch's 20 wires (one barrier)
    if (tid < N_WIRES) {
        float h = (x[b * N_WIRES + tid] + params[tid]) * 0.5f;
        float c, s;
        sincosf(h, &s, &c);
        sc[tid] = c;
        ss[tid] = s;
    }
    __syncthreads();

    // 2) lo part: this thread covers lo = 4*tid + j, j=0..3.
    //    lo bit q (q=2..9) = tid bit (q-2); factor = ss[19-q] : sc[19-q].
    float lo_common = 1.0f;
    #pragma unroll
    for (int q = 2; q < 10; q++)
        lo_common *= ((tid >> (q - 2)) & 1) ? ss[19 - q] : sc[19 - q];

    // j bit0 -> wire 19, j bit1 -> wire 18
    float lv0 = sc[19] * sc[18];   // j=0
    float lv1 = ss[19] * sc[18];   // j=1
    float lv2 = sc[19] * ss[18];   // j=2
    float lv3 = ss[19] * ss[18];   // j=3

    // 3) hi part: hi = 4*bx + i, i=0..3.
    //    hi bit q (q=2..9) = bx bit (q-2); factor = ss[9-q] : sc[9-q].
    float hi_common = 1.0f;
    #pragma unroll
    for (int q = 2; q < 10; q++)
        hi_common *= ((bx >> (q - 2)) & 1) ? ss[9 - q] : sc[9 - q];

    // i bit0 -> wire 9, i bit1 -> wire 8
    float hv[4];
    hv[0] = sc[9] * sc[8];     // i=0
    hv[1] = ss[9] * sc[8];     // i=1
    hv[2] = sc[9] * ss[8];     // i=2
    hv[3] = ss[9] * ss[8];     // i=3

    float base = lo_common * hi_common;
    float c0 = base * lv0, c1 = base * lv1, c2 = base * lv2, c3 = base * lv3;

    // 4) stream out: 4 hi-values x one float4/thread (independent stores)
    size_t off = ((size_t)b << 20) + ((size_t)bx << 12);
    float4* dst = reinterpret_cast<float4*>(out + off) + tid;

    #pragma unroll
    for (int i = 0; i < HI_PER_BLOCK; i++) {
        float ph = hv[i];
        float4 v;
        v.x = ph * c0;
        v.y = ph * c1;
        v.z = ph * c2;
        v.w = ph * c3;
        __stcs(dst + i * 256, v);    // streaming store: write-once output
    }
}

extern "C" void kernel_launch(void* const* d_in, const int* in_sizes, int n_in,
                              void* d_out, int out_size)
{
    const float* x      = (const float*)d_in[0];   // (64, 20)
    const float* params = (const float*)d_in[1];   // (20,)
    float* out          = (float*)d_out;           // (64, 2^20)

    dim3 grid(1024 / HI_PER_BLOCK, BATCH);         // (256, 64) = 16384 CTAs
    qansatz_kernel<<<grid, THREADS>>>(x, params, out);
}